// round 16
// baseline (speedup 1.0000x reference)
#include <cuda_runtime.h>
#include <cuda_fp16.h>
#include <math.h>
#include <stdint.h>

// Problem dims
#define S_LEN 256
#define B_SZ  128
#define D1    1024
#define N2    2048
#define M_ROWS (S_LEN * B_SZ)   // 32768

// ---------------- device scratch (static; no allocations allowed) ----------------
__device__ __half g_Ah[(size_t)M_ROWS * D1];     // f1_seq in fp16            (64 MB)
__device__ __half g_Wt[(size_t)N2 * D1];         // [W11a|W12a]^T : [n][k]    (4 MB)
__device__ __half g_Wbt[(size_t)N2 * D1];        // blockdiag bottom halves^T (4 MB)
__device__ __half g_A2h[(size_t)B_SZ * N2];      // [f1 | f2] fp16
__device__ float  g_c[(size_t)B_SZ * N2];        // bias + S-independent pre-activation
__device__ float  g_wv[N2];                      // [W21 | W22]
__device__ float  g_logit[2 * M_ROWS];           // s1, s2 logits
__device__ int    g_done;                        // small-gemm completion counter

// ---------------- PTX helpers (all sm_80-era; safe under compute_100) ----------------
__device__ __forceinline__ uint32_t smem_u32(const void* p) {
    uint32_t a;
    asm("{ .reg .u64 t; cvta.to.shared.u64 t, %1; cvt.u32.u64 %0, t; }" : "=r"(a) : "l"(p));
    return a;
}
__device__ __forceinline__ void cp16(uint32_t s, const void* g) {
    asm volatile("cp.async.cg.shared.global [%0], [%1], 16;" :: "r"(s), "l"(g));
}
__device__ __forceinline__ void cp_commit() { asm volatile("cp.async.commit_group;" ::: "memory"); }
__device__ __forceinline__ void ldsm4(uint32_t& r0, uint32_t& r1, uint32_t& r2, uint32_t& r3,
                                      uint32_t addr) {
    asm volatile("ldmatrix.sync.aligned.m8n8.x4.shared.b16 {%0,%1,%2,%3}, [%4];"
                 : "=r"(r0), "=r"(r1), "=r"(r2), "=r"(r3) : "r"(addr));
}
__device__ __forceinline__ void mma16816(float* c, uint32_t a0, uint32_t a1, uint32_t a2,
                                         uint32_t a3, uint32_t b0, uint32_t b1) {
    asm volatile(
        "mma.sync.aligned.m16n8k16.row.col.f32.f16.f16.f32 "
        "{%0,%1,%2,%3}, {%4,%5,%6,%7}, {%8,%9}, {%0,%1,%2,%3};"
        : "+f"(c[0]), "+f"(c[1]), "+f"(c[2]), "+f"(c[3])
        : "r"(a0), "r"(a1), "r"(a2), "r"(a3), "r"(b0), "r"(b1));
}
__device__ __forceinline__ float tanh_fast(float x) {
    float t;
    asm("tanh.approx.f32 %0, %1;" : "=f"(t) : "f"(x));
    return t;
}

// ---- prep (merged, block-specialized):
//   blocks [0, 2048): 32x32 tiled transpose of W11/W12 -> g_Wt, g_Wbt
//   blocks [2048, 6144): grid-stride conversions + zero out/g_logit/g_done
#define TRANS_BLOCKS 2048
#define PREP_BLOCKS  4096
__global__ void prep_kernel(const float* __restrict__ fseq,
                            const float* __restrict__ f1, const float* __restrict__ f2,
                            const float* __restrict__ b11, const float* __restrict__ b12,
                            const float* __restrict__ W21, const float* __restrict__ W22,
                            const float* __restrict__ W11, const float* __restrict__ W12,
                            float* __restrict__ out) {
    int tid = threadIdx.x;
    if (blockIdx.x < TRANS_BLOCKS) {
        __shared__ float st[32][33], sb[32][33];
        int bx = blockIdx.x;
        int k0 = (bx & 31) * 32;            // k tile (0..1023)
        int n0 = (bx >> 5) * 32;            // n tile (0..2047)
        const float* W = (n0 < D1) ? W11 : W12;
        int nc = (n0 < D1) ? n0 : n0 - D1;
        int tx = tid & 31, ty = tid >> 5;   // (32, 8) mapping
#pragma unroll
        for (int j = 0; j < 4; j++) {
            int k = k0 + ty + j * 8;
            st[ty + j * 8][tx] = W[(size_t)k * D1 + nc + tx];
            sb[ty + j * 8][tx] = W[(size_t)(D1 + k) * D1 + nc + tx];
        }
        __syncthreads();
#pragma unroll
        for (int j = 0; j < 4; j++) {
            int n = n0 + ty + j * 8;
            g_Wt[(size_t)n * D1 + k0 + tx]  = __float2half_rn(st[tx][ty + j * 8]);
            g_Wbt[(size_t)n * D1 + k0 + tx] = __float2half_rn(sb[tx][ty + j * 8]);
        }
        return;
    }

    size_t stride = (size_t)PREP_BLOCKS * blockDim.x;
    size_t gid = (size_t)(blockIdx.x - TRANS_BLOCKS) * blockDim.x + tid;
    if (gid == 0) g_done = 0;               // reset producer counter (graph-replay safe)

    size_t n4 = (size_t)M_ROWS * D1 / 4;
    const float4* src = (const float4*)fseq;
    __half2* dst = (__half2*)g_Ah;
    for (size_t i = gid; i < n4; i += stride) {
        float4 v = src[i];
        dst[2 * i]     = __floats2half2_rn(v.x, v.y);
        dst[2 * i + 1] = __floats2half2_rn(v.z, v.w);
    }
    for (size_t i = gid; i < B_SZ * N2; i += stride) {
        int b = (int)(i >> 11), k = (int)(i & (N2 - 1));
        float v, bias;
        if (k < D1) { v = f1[b * D1 + k]; bias = b11[k]; }
        else        { v = f2[b * D1 + (k - D1)]; bias = b12[k - D1]; }
        g_A2h[i] = __float2half_rn(v);
        g_c[i] = bias;
    }
    for (size_t i = gid; i < 2 * M_ROWS; i += stride) g_logit[i] = 0.f;
    for (size_t i = gid; i < B_SZ * D1; i += stride) out[i] = 0.f;   // atomics target
    for (size_t i = gid; i < N2; i += stride)
        g_wv[i] = (i < D1) ? W21[i] : W22[i - D1];
}

// ---------------- shared GEMM machinery (128x128 tile, 32x64 warp tile) -----------
#define KCHUNK 64
#define NCHUNKS 16                         // 1024 / 64
#define NSTAGE 3
#define LDS_PAD 72                         // halfs per row (64 + 8)
#define A_SZ (128 * LDS_PAD * 2)           // 18432 B
#define STAGE_BYTES (2 * A_SZ)             // A + B = 36864 B
#define SMEM_BYTES_MAIN (NSTAGE * STAGE_BYTES)  // 110592 B

__device__ __forceinline__ void load_chunk_g(uint32_t sbase, int st, const __half* Ag, int lda,
                                             const __half* Bg, int tid) {
    uint32_t abase = sbase + st * STAGE_BYTES;
    uint32_t bbase = abase + A_SZ;
#pragma unroll
    for (int j = 0; j < 4; j++) {
        int idx = tid + j * 256;
        int r = idx >> 3, cc = idx & 7;
        cp16(abase + (r * LDS_PAD + cc * 8) * 2, Ag + (size_t)r * lda + cc * 8);
    }
#pragma unroll
    for (int j = 0; j < 4; j++) {
        int idx = tid + j * 256;
        int r = idx >> 3, cc = idx & 7;
        cp16(bbase + (r * LDS_PAD + cc * 8) * 2, Bg + (size_t)r * D1 + cc * 8);
    }
    cp_commit();
}

// 3-stage pipelined mainloop — R11 winner form: warp-parity de-phasing (wid&1),
// compiler-scheduled LDSM batches, prefetch spread 2-per-ks.
template <int NC>
__device__ __forceinline__ void gemm_mainloop(float acc[2][8][4], uint32_t sbase,
                                              uint32_t a_off, uint32_t b_off,
                                              const __half* Ag, int lda, const __half* Bg,
                                              int tid) {
    const int ksx = ((tid >> 5) & 1) << 1;   // warp-parity ks phase offset (0 or 2)
    load_chunk_g(sbase, 0, Ag, lda, Bg, tid);
    if (NC > 1) load_chunk_g(sbase, 1, Ag + KCHUNK, lda, Bg + KCHUNK, tid);
    for (int kt = 0; kt < NC; kt++) {
        if (kt < NC - 1) asm volatile("cp.async.wait_group 1;" ::: "memory");
        else             asm volatile("cp.async.wait_group 0;" ::: "memory");
        __syncthreads();

        const bool pf = (kt + 2 < NC);
        const __half* An = Ag + (kt + 2) * KCHUNK;
        const __half* Bn = Bg + (kt + 2) * KCHUNK;
        uint32_t nabase = sbase + ((kt + 2) % NSTAGE) * STAGE_BYTES;
        uint32_t nbbase = nabase + A_SZ;
        const int pr = tid >> 3, pc = tid & 7;          // prefetch row/col within j-slab

        uint32_t sA = sbase + (kt % NSTAGE) * STAGE_BYTES;
        uint32_t sB = sA + A_SZ;
#pragma unroll
        for (int ks = 0; ks < 4; ks++) {
            if (pf) {   // 2 of 8 prefetch cp.asyncs per ks iter (spread L1 pressure)
                int r = pr + ks * 32;
                cp16(nabase + (r * LDS_PAD + pc * 8) * 2, An + (size_t)r * lda + pc * 8);
                cp16(nbbase + (r * LDS_PAD + pc * 8) * 2, Bn + (size_t)r * D1 + pc * 8);
            }
            const int kss = (ks + ksx) & 3;             // de-phased k-step
            uint32_t a[2][4];
#pragma unroll
            for (int mi = 0; mi < 2; mi++)
                ldsm4(a[mi][0], a[mi][1], a[mi][2], a[mi][3],
                      sA + (a_off + mi * 16 * LDS_PAD + kss * 16) * 2);
            uint32_t b[4][4];
#pragma unroll
            for (int p = 0; p < 4; p++)
                ldsm4(b[p][0], b[p][1], b[p][2], b[p][3],
                      sB + (b_off + p * 16 * LDS_PAD + kss * 16) * 2);
#pragma unroll
            for (int mi = 0; mi < 2; mi++)
#pragma unroll
                for (int ni = 0; ni < 8; ni++) {
                    int p = ni >> 1, h = (ni & 1) * 2;
                    mma16816(acc[mi][ni], a[mi][0], a[mi][1], a[mi][2], a[mi][3],
                             b[p][h], b[p][h + 1]);
                }
        }
        if (pf) cp_commit();
    }
}

// ---------------- fused GEMM kernel: 1D grid 4224 ----------------
//   blocks [0, 128):   small GEMM (g_c += [f1|f2] @ blockdiag, split-K 8) -> arrive g_done
//   blocks [128, 4224): main GEMM; epilogue waits for g_done == 128 before reading g_c
#define SMALL_BLOCKS 128
__global__ void __launch_bounds__(256, 2) fused_gemm_kernel() {
    extern __shared__ char smem[];
    uint32_t sbase = smem_u32(smem);
    const int tid = threadIdx.x;
    const int lane = tid & 31;
    const int wid = tid >> 5;
    const int mw = (wid & 3) * 32;
    const int nw = (wid >> 2) * 64;

    const uint32_t a_off = (uint32_t)(mw + (lane & 15)) * LDS_PAD + (lane >> 4) * 8;
    const uint32_t b_off = (uint32_t)(nw + (lane & 7) + ((lane >> 4) & 1) * 8) * LDS_PAD +
                           ((lane >> 3) & 1) * 8;

    float acc[2][8][4];
#pragma unroll
    for (int mi = 0; mi < 2; mi++)
#pragma unroll
        for (int ni = 0; ni < 8; ni++)
#pragma unroll
            for (int q = 0; q < 4; q++) acc[mi][ni][q] = 0.f;

    const int gid = lane >> 2, tig = lane & 3;

    if (blockIdx.x < SMALL_BLOCKS) {
        // ---- small GEMM: bid -> (n tile, k split) ----
        const int n0 = (blockIdx.x & 15) * 128;
        const int kz = (blockIdx.x >> 4) * 2;
        const int aoff = (n0 >= D1) ? D1 : 0;
        const __half* Ag = g_A2h + aoff + kz * KCHUNK;
        const __half* Bg = g_Wbt + (size_t)n0 * D1 + kz * KCHUNK;

        gemm_mainloop<2>(acc, sbase, a_off, b_off, Ag, N2, Bg, tid);

#pragma unroll
        for (int mi = 0; mi < 2; mi++)
#pragma unroll
            for (int ni = 0; ni < 8; ni++) {
                int colL = nw + ni * 8 + 2 * tig;
                int r0 = mw + mi * 16 + gid;
                const float* a = acc[mi][ni];
                float* p0 = g_c + (size_t)r0 * N2 + n0 + colL;
                float* p1 = g_c + (size_t)(r0 + 8) * N2 + n0 + colL;
                atomicAdd(p0, a[0]);     atomicAdd(p0 + 1, a[1]);
                atomicAdd(p1, a[2]);     atomicAdd(p1 + 1, a[3]);
            }
        __threadfence();
        __syncthreads();
        if (tid == 0) atomicAdd(&g_done, 1);
        return;
    }

    // ---- main GEMM: bid-128 -> (n fast, m slow) for A L2 reuse ----
    const int bid = blockIdx.x - SMALL_BLOCKS;
    const int n0 = (bid & 15) * 128;
    const int m0 = (bid >> 4) * 128;

    const __half* Ag = g_Ah + (size_t)m0 * D1;
    const __half* Bg = g_Wt + (size_t)n0 * D1;

    gemm_mainloop<NCHUNKS>(acc, sbase, a_off, b_off, Ag, D1, Bg, tid);

    // wait for small-GEMM producers (long since done in steady state)
    if (tid == 0) {
        while (atomicAdd(&g_done, 0) < SMALL_BLOCKS) __nanosleep(200);
    }
    __syncthreads();

    // ---- register epilogue: tanh(x + c) . wv, reduced over N ----
    float rs[2][2] = {{0.f, 0.f}, {0.f, 0.f}};
#pragma unroll
    for (int ni = 0; ni < 8; ni++) {
        int col = n0 + nw + ni * 8 + 2 * tig;
        float2 wv2 = *(const float2*)(g_wv + col);
#pragma unroll
        for (int mi = 0; mi < 2; mi++) {
            int r0 = mw + mi * 16 + gid;
            float2 c0 = *(const float2*)(g_c + (size_t)r0 * N2 + col);
            float2 c1 = *(const float2*)(g_c + (size_t)(r0 + 8) * N2 + col);
            const float* a = acc[mi][ni];
            rs[mi][0] += tanh_fast(a[0] + c0.x) * wv2.x;
            rs[mi][0] += tanh_fast(a[1] + c0.y) * wv2.y;
            rs[mi][1] += tanh_fast(a[2] + c1.x) * wv2.x;
            rs[mi][1] += tanh_fast(a[3] + c1.y) * wv2.y;
        }
    }
    int sel = (n0 >= D1) ? M_ROWS : 0;
#pragma unroll
    for (int mi = 0; mi < 2; mi++)
#pragma unroll
        for (int h = 0; h < 2; h++) {
            float v = rs[mi][h];
            v += __shfl_xor_sync(0xffffffffu, v, 1);
            v += __shfl_xor_sync(0xffffffffu, v, 2);
            if (tig == 0) {
                int b = mw + mi * 16 + gid + h * 8;
                atomicAdd(&g_logit[sel + m0 + b], v);
            }
        }
}

// ------ fused softmax + weighted sum: grid (2, 128, 8) ------
#define SPLIT_Z 8
#define S_PER_Z (S_LEN / SPLIT_Z)   // 32
__global__ void __launch_bounds__(256) softmax_wsum_kernel(float* __restrict__ out) {
    int b = blockIdx.y;
    int tid = threadIdx.x;   // 256 threads == S_LEN
    int lane = tid & 31, wrp = tid >> 5;
    __shared__ float as[S_LEN];
    __shared__ float red[4][8];
    float v1 = g_logit[tid * B_SZ + b];
    float v2 = g_logit[M_ROWS + tid * B_SZ + b];

    float w1 = v1, w2 = v2;
#pragma unroll
    for (int o = 16; o; o >>= 1) {
        w1 = fmaxf(w1, __shfl_xor_sync(0xffffffffu, w1, o));
        w2 = fmaxf(w2, __shfl_xor_sync(0xffffffffu, w2, o));
    }
    if (lane == 0) { red[0][wrp] = w1; red[1][wrp] = w2; }
    __syncthreads();
    float m1 = red[0][0], m2 = red[1][0];
#pragma unroll
    for (int i = 1; i < 8; i++) { m1 = fmaxf(m1, red[0][i]); m2 = fmaxf(m2, red[1][i]); }

    float e1 = expf(v1 - m1), e2 = expf(v2 - m2);
    float s1 = e1, s2 = e2;
#pragma unroll
    for (int o = 16; o; o >>= 1) {
        s1 += __shfl_xor_sync(0xffffffffu, s1, o);
        s2 += __shfl_xor_sync(0xffffffffu, s2, o);
    }
    if (lane == 0) { red[2][wrp] = s1; red[3][wrp] = s2; }
    __syncthreads();
    float z1 = 0.f, z2 = 0.f;
#pragma unroll
    for (int i = 0; i < 8; i++) { z1 += red[2][i]; z2 += red[3][i]; }

    as[tid] = (e1 / z1 + e2 / z2) * 0.5f / (float)S_LEN;
    __syncthreads();

    int d2 = blockIdx.x * 256 + tid;        // half2 index: 512 per b
    int s0 = blockIdx.z * S_PER_Z;
    const __half2* p = (const __half2*)g_Ah + (size_t)s0 * B_SZ * (D1 / 2) +
                       (size_t)b * (D1 / 2) + d2;
    float ax = 0.f, ay = 0.f;
#pragma unroll 16
    for (int s = 0; s < S_PER_Z; s++) {
        float2 v = __half22float2(p[(size_t)s * B_SZ * (D1 / 2)]);
        float w = as[s0 + s];
        ax += w * v.x; ay += w * v.y;
    }
    float* o = out + (size_t)b * D1 + d2 * 2;
    atomicAdd(o, ax);
    atomicAdd(o + 1, ay);
}

// ---------------- launch ----------------
extern "C" void kernel_launch(void* const* d_in, const int* in_sizes, int n_in,
                              void* d_out, int out_size) {
    const float* f1   = (const float*)d_in[0];
    const float* f2   = (const float*)d_in[1];
    const float* fseq = (const float*)d_in[2];
    const float* W11  = (const float*)d_in[3];
    const float* b11  = (const float*)d_in[4];
    const float* W12  = (const float*)d_in[5];
    const float* b12  = (const float*)d_in[6];
    const float* W21  = (const float*)d_in[7];
    const float* W22  = (const float*)d_in[9];
    float* out = (float*)d_out;

    cudaFuncSetAttribute(fused_gemm_kernel, cudaFuncAttributeMaxDynamicSharedMemorySize,
                         SMEM_BYTES_MAIN);

    prep_kernel<<<TRANS_BLOCKS + PREP_BLOCKS, 256>>>(fseq, f1, f2, b11, b12, W21, W22,
                                                     W11, W12, out);
    fused_gemm_kernel<<<SMALL_BLOCKS + 16 * 256, 256, SMEM_BYTES_MAIN>>>();
    softmax_wsum_kernel<<<dim3(2, 128, SPLIT_Z), 256>>>(out);
}

// round 17
// speedup vs baseline: 1.0489x; 1.0489x over previous
#include <cuda_runtime.h>
#include <cuda_fp16.h>
#include <math.h>
#include <stdint.h>

// Problem dims
#define S_LEN 256
#define B_SZ  128
#define D1    1024
#define N2    2048
#define M_ROWS (S_LEN * B_SZ)   // 32768

// ---------------- device scratch (static; no allocations allowed) ----------------
__device__ __half g_Ah[(size_t)M_ROWS * D1];     // f1_seq in fp16            (64 MB)
__device__ __half g_Wt[(size_t)N2 * D1];         // [W11a|W12a]^T : [n][k]    (4 MB)
__device__ __half g_Wbt[(size_t)N2 * D1];        // blockdiag bottom halves^T (4 MB)
__device__ __half g_A2h[(size_t)B_SZ * N2];      // [f1 | f2] fp16
__device__ float  g_c[(size_t)B_SZ * N2];        // bias + S-independent pre-activation
__device__ float  g_wv[N2];                      // [W21 | W22]
__device__ float  g_logit[2 * M_ROWS];           // s1, s2 logits

// ---------------- PTX helpers (all sm_80-era; safe under compute_100) ----------------
__device__ __forceinline__ uint32_t smem_u32(const void* p) {
    uint32_t a;
    asm("{ .reg .u64 t; cvta.to.shared.u64 t, %1; cvt.u32.u64 %0, t; }" : "=r"(a) : "l"(p));
    return a;
}
__device__ __forceinline__ void cp16(uint32_t s, const void* g) {
    asm volatile("cp.async.cg.shared.global [%0], [%1], 16;" :: "r"(s), "l"(g));
}
__device__ __forceinline__ void cp_commit() { asm volatile("cp.async.commit_group;" ::: "memory"); }
__device__ __forceinline__ void ldsm4(uint32_t& r0, uint32_t& r1, uint32_t& r2, uint32_t& r3,
                                      uint32_t addr) {
    asm volatile("ldmatrix.sync.aligned.m8n8.x4.shared.b16 {%0,%1,%2,%3}, [%4];"
                 : "=r"(r0), "=r"(r1), "=r"(r2), "=r"(r3) : "r"(addr));
}
__device__ __forceinline__ void mma16816(float* c, uint32_t a0, uint32_t a1, uint32_t a2,
                                         uint32_t a3, uint32_t b0, uint32_t b1) {
    asm volatile(
        "mma.sync.aligned.m16n8k16.row.col.f32.f16.f16.f32 "
        "{%0,%1,%2,%3}, {%4,%5,%6,%7}, {%8,%9}, {%0,%1,%2,%3};"
        : "+f"(c[0]), "+f"(c[1]), "+f"(c[2]), "+f"(c[3])
        : "r"(a0), "r"(a1), "r"(a2), "r"(a3), "r"(b0), "r"(b1));
}
__device__ __forceinline__ float tanh_fast(float x) {
    float t;
    asm("tanh.approx.f32 %0, %1;" : "=f"(t) : "f"(x));
    return t;
}

// ---- prep (merged, block-specialized):
//   blocks [0, 2048): 32x32 tiled transpose of W11/W12 -> g_Wt, g_Wbt
//   blocks [2048, 6144): grid-stride conversions + zero out/g_logit
#define TRANS_BLOCKS 2048
#define PREP_BLOCKS  4096
__global__ void prep_kernel(const float* __restrict__ fseq,
                            const float* __restrict__ f1, const float* __restrict__ f2,
                            const float* __restrict__ b11, const float* __restrict__ b12,
                            const float* __restrict__ W21, const float* __restrict__ W22,
                            const float* __restrict__ W11, const float* __restrict__ W12,
                            float* __restrict__ out) {
    int tid = threadIdx.x;
    if (blockIdx.x < TRANS_BLOCKS) {
        __shared__ float st[32][33], sb[32][33];
        int bx = blockIdx.x;
        int k0 = (bx & 31) * 32;            // k tile (0..1023)
        int n0 = (bx >> 5) * 32;            // n tile (0..2047)
        const float* W = (n0 < D1) ? W11 : W12;
        int nc = (n0 < D1) ? n0 : n0 - D1;
        int tx = tid & 31, ty = tid >> 5;   // (32, 8) mapping
#pragma unroll
        for (int j = 0; j < 4; j++) {
            int k = k0 + ty + j * 8;
            st[ty + j * 8][tx] = W[(size_t)k * D1 + nc + tx];
            sb[ty + j * 8][tx] = W[(size_t)(D1 + k) * D1 + nc + tx];
        }
        __syncthreads();
#pragma unroll
        for (int j = 0; j < 4; j++) {
            int n = n0 + ty + j * 8;
            g_Wt[(size_t)n * D1 + k0 + tx]  = __float2half_rn(st[tx][ty + j * 8]);
            g_Wbt[(size_t)n * D1 + k0 + tx] = __float2half_rn(sb[tx][ty + j * 8]);
        }
        return;
    }

    size_t stride = (size_t)PREP_BLOCKS * blockDim.x;
    size_t gid = (size_t)(blockIdx.x - TRANS_BLOCKS) * blockDim.x + tid;

    size_t n4 = (size_t)M_ROWS * D1 / 4;
    const float4* src = (const float4*)fseq;
    __half2* dst = (__half2*)g_Ah;
    for (size_t i = gid; i < n4; i += stride) {
        float4 v = src[i];
        dst[2 * i]     = __floats2half2_rn(v.x, v.y);
        dst[2 * i + 1] = __floats2half2_rn(v.z, v.w);
    }
    for (size_t i = gid; i < B_SZ * N2; i += stride) {
        int b = (int)(i >> 11), k = (int)(i & (N2 - 1));
        float v, bias;
        if (k < D1) { v = f1[b * D1 + k]; bias = b11[k]; }
        else        { v = f2[b * D1 + (k - D1)]; bias = b12[k - D1]; }
        g_A2h[i] = __float2half_rn(v);
        g_c[i] = bias;
    }
    for (size_t i = gid; i < 2 * M_ROWS; i += stride) g_logit[i] = 0.f;
    for (size_t i = gid; i < B_SZ * D1; i += stride) out[i] = 0.f;   // atomics target
    for (size_t i = gid; i < N2; i += stride)
        g_wv[i] = (i < D1) ? W21[i] : W22[i - D1];
}

// ---------------- shared GEMM machinery (128x128 tile, 32x64 warp tile) -----------
#define KCHUNK 64
#define NCHUNKS 16                         // 1024 / 64
#define NSTAGE 3
#define LDS_PAD 72                         // halfs per row (64 + 8)
#define A_SZ (128 * LDS_PAD * 2)           // 18432 B
#define STAGE_BYTES (2 * A_SZ)             // A + B = 36864 B
#define SMEM_BYTES_MAIN (NSTAGE * STAGE_BYTES)  // 110592 B

__device__ __forceinline__ void load_chunk_g(uint32_t sbase, int st, const __half* Ag, int lda,
                                             const __half* Bg, int tid) {
    uint32_t abase = sbase + st * STAGE_BYTES;
    uint32_t bbase = abase + A_SZ;
#pragma unroll
    for (int j = 0; j < 4; j++) {
        int idx = tid + j * 256;
        int r = idx >> 3, cc = idx & 7;
        cp16(abase + (r * LDS_PAD + cc * 8) * 2, Ag + (size_t)r * lda + cc * 8);
    }
#pragma unroll
    for (int j = 0; j < 4; j++) {
        int idx = tid + j * 256;
        int r = idx >> 3, cc = idx & 7;
        cp16(bbase + (r * LDS_PAD + cc * 8) * 2, Bg + (size_t)r * D1 + cc * 8);
    }
    cp_commit();
}

// 3-stage pipelined mainloop — R11 winner form: warp-parity de-phasing (wid&1),
// compiler-scheduled LDSM batches, prefetch spread 2-per-ks.
template <int NC>
__device__ __forceinline__ void gemm_mainloop(float acc[2][8][4], uint32_t sbase,
                                              uint32_t a_off, uint32_t b_off,
                                              const __half* Ag, int lda, const __half* Bg,
                                              int tid) {
    const int ksx = ((tid >> 5) & 1) << 1;   // warp-parity ks phase offset (0 or 2)
    load_chunk_g(sbase, 0, Ag, lda, Bg, tid);
    if (NC > 1) load_chunk_g(sbase, 1, Ag + KCHUNK, lda, Bg + KCHUNK, tid);
    for (int kt = 0; kt < NC; kt++) {
        if (kt < NC - 1) asm volatile("cp.async.wait_group 1;" ::: "memory");
        else             asm volatile("cp.async.wait_group 0;" ::: "memory");
        __syncthreads();

        const bool pf = (kt + 2 < NC);
        const __half* An = Ag + (kt + 2) * KCHUNK;
        const __half* Bn = Bg + (kt + 2) * KCHUNK;
        uint32_t nabase = sbase + ((kt + 2) % NSTAGE) * STAGE_BYTES;
        uint32_t nbbase = nabase + A_SZ;
        const int pr = tid >> 3, pc = tid & 7;          // prefetch row/col within j-slab

        uint32_t sA = sbase + (kt % NSTAGE) * STAGE_BYTES;
        uint32_t sB = sA + A_SZ;
#pragma unroll
        for (int ks = 0; ks < 4; ks++) {
            if (pf) {   // 2 of 8 prefetch cp.asyncs per ks iter (spread L1 pressure)
                int r = pr + ks * 32;
                cp16(nabase + (r * LDS_PAD + pc * 8) * 2, An + (size_t)r * lda + pc * 8);
                cp16(nbbase + (r * LDS_PAD + pc * 8) * 2, Bn + (size_t)r * D1 + pc * 8);
            }
            const int kss = (ks + ksx) & 3;             // de-phased k-step
            uint32_t a[2][4];
#pragma unroll
            for (int mi = 0; mi < 2; mi++)
                ldsm4(a[mi][0], a[mi][1], a[mi][2], a[mi][3],
                      sA + (a_off + mi * 16 * LDS_PAD + kss * 16) * 2);
            uint32_t b[4][4];
#pragma unroll
            for (int p = 0; p < 4; p++)
                ldsm4(b[p][0], b[p][1], b[p][2], b[p][3],
                      sB + (b_off + p * 16 * LDS_PAD + kss * 16) * 2);
#pragma unroll
            for (int mi = 0; mi < 2; mi++)
#pragma unroll
                for (int ni = 0; ni < 8; ni++) {
                    int p = ni >> 1, h = (ni & 1) * 2;
                    mma16816(acc[mi][ni], a[mi][0], a[mi][1], a[mi][2], a[mi][3],
                             b[p][h], b[p][h + 1]);
                }
        }
        if (pf) cp_commit();
    }
}

// ---------------- small GEMM: g_c += [f1|f2] @ blockdiag, split-K 8 -------------
__global__ void __launch_bounds__(256, 2) small_gemm_kernel() {
    extern __shared__ char smem[];
    uint32_t sbase = smem_u32(smem);
    const int tid = threadIdx.x;
    const int lane = tid & 31;
    const int wid = tid >> 5;
    const int mw = (wid & 3) * 32;
    const int nw = (wid >> 2) * 64;
    const int n0 = blockIdx.x * 128;
    const int kz = blockIdx.z * 2;
    const int aoff = (n0 >= D1) ? D1 : 0;

    const uint32_t a_off = (uint32_t)(mw + (lane & 15)) * LDS_PAD + (lane >> 4) * 8;
    const uint32_t b_off = (uint32_t)(nw + (lane & 7) + ((lane >> 4) & 1) * 8) * LDS_PAD +
                           ((lane >> 3) & 1) * 8;

    float acc[2][8][4];
#pragma unroll
    for (int mi = 0; mi < 2; mi++)
#pragma unroll
        for (int ni = 0; ni < 8; ni++)
#pragma unroll
            for (int q = 0; q < 4; q++) acc[mi][ni][q] = 0.f;

    const __half* Ag = g_A2h + aoff + kz * KCHUNK;
    const __half* Bg = g_Wbt + (size_t)n0 * D1 + kz * KCHUNK;

    gemm_mainloop<2>(acc, sbase, a_off, b_off, Ag, N2, Bg, tid);

    const int gid = lane >> 2, tig = lane & 3;
#pragma unroll
    for (int mi = 0; mi < 2; mi++)
#pragma unroll
        for (int ni = 0; ni < 8; ni++) {
            int colL = nw + ni * 8 + 2 * tig;
            int r0 = mw + mi * 16 + gid;
            const float* a = acc[mi][ni];
            float* p0 = g_c + (size_t)r0 * N2 + n0 + colL;
            float* p1 = g_c + (size_t)(r0 + 8) * N2 + n0 + colL;
            atomicAdd(p0, a[0]);     atomicAdd(p0 + 1, a[1]);
            atomicAdd(p1, a[2]);     atomicAdd(p1 + 1, a[3]);
        }
}

// ---------------- main GEMM + fused tanh-dot register epilogue ----------
__global__ void __launch_bounds__(256, 2) main_gemm_kernel() {
    extern __shared__ char smem[];
    uint32_t sbase = smem_u32(smem);
    const int tid = threadIdx.x;
    const int lane = tid & 31;
    const int wid = tid >> 5;
    const int mw = (wid & 3) * 32;
    const int nw = (wid >> 2) * 64;
    const int m0 = blockIdx.y * 128;
    const int n0 = blockIdx.x * 128;

    const uint32_t a_off = (uint32_t)(mw + (lane & 15)) * LDS_PAD + (lane >> 4) * 8;
    const uint32_t b_off = (uint32_t)(nw + (lane & 7) + ((lane >> 4) & 1) * 8) * LDS_PAD +
                           ((lane >> 3) & 1) * 8;

    float acc[2][8][4];
#pragma unroll
    for (int mi = 0; mi < 2; mi++)
#pragma unroll
        for (int ni = 0; ni < 8; ni++)
#pragma unroll
            for (int q = 0; q < 4; q++) acc[mi][ni][q] = 0.f;

    const __half* Ag = g_Ah + (size_t)m0 * D1;
    const __half* Bg = g_Wt + (size_t)n0 * D1;

    gemm_mainloop<NCHUNKS>(acc, sbase, a_off, b_off, Ag, D1, Bg, tid);

    // ---- register epilogue: tanh(x + c) . wv, reduced over N ----
    const int gid = lane >> 2, tig = lane & 3;
    float rs[2][2] = {{0.f, 0.f}, {0.f, 0.f}};
#pragma unroll
    for (int ni = 0; ni < 8; ni++) {
        int col = n0 + nw + ni * 8 + 2 * tig;
        float2 wv2 = *(const float2*)(g_wv + col);
#pragma unroll
        for (int mi = 0; mi < 2; mi++) {
            int r0 = mw + mi * 16 + gid;
            float2 c0 = *(const float2*)(g_c + (size_t)r0 * N2 + col);
            float2 c1 = *(const float2*)(g_c + (size_t)(r0 + 8) * N2 + col);
            const float* a = acc[mi][ni];
            rs[mi][0] += tanh_fast(a[0] + c0.x) * wv2.x;
            rs[mi][0] += tanh_fast(a[1] + c0.y) * wv2.y;
            rs[mi][1] += tanh_fast(a[2] + c1.x) * wv2.x;
            rs[mi][1] += tanh_fast(a[3] + c1.y) * wv2.y;
        }
    }
    int sel = (n0 >= D1) ? M_ROWS : 0;
#pragma unroll
    for (int mi = 0; mi < 2; mi++)
#pragma unroll
        for (int h = 0; h < 2; h++) {
            float v = rs[mi][h];
            v += __shfl_xor_sync(0xffffffffu, v, 1);
            v += __shfl_xor_sync(0xffffffffu, v, 2);
            if (tig == 0) {
                int b = mw + mi * 16 + gid + h * 8;
                atomicAdd(&g_logit[sel + blockIdx.y * B_SZ + b], v);
            }
        }
}

// ------ fused softmax + weighted sum: grid (2, 128, 8) ------
#define SPLIT_Z 8
#define S_PER_Z (S_LEN / SPLIT_Z)   // 32
__global__ void __launch_bounds__(256) softmax_wsum_kernel(float* __restrict__ out) {
    int b = blockIdx.y;
    int tid = threadIdx.x;   // 256 threads == S_LEN
    int lane = tid & 31, wrp = tid >> 5;
    __shared__ float as[S_LEN];
    __shared__ float red[4][8];
    float v1 = g_logit[tid * B_SZ + b];
    float v2 = g_logit[M_ROWS + tid * B_SZ + b];

    float w1 = v1, w2 = v2;
#pragma unroll
    for (int o = 16; o; o >>= 1) {
        w1 = fmaxf(w1, __shfl_xor_sync(0xffffffffu, w1, o));
        w2 = fmaxf(w2, __shfl_xor_sync(0xffffffffu, w2, o));
    }
    if (lane == 0) { red[0][wrp] = w1; red[1][wrp] = w2; }
    __syncthreads();
    float m1 = red[0][0], m2 = red[1][0];
#pragma unroll
    for (int i = 1; i < 8; i++) { m1 = fmaxf(m1, red[0][i]); m2 = fmaxf(m2, red[1][i]); }

    float e1 = expf(v1 - m1), e2 = expf(v2 - m2);
    float s1 = e1, s2 = e2;
#pragma unroll
    for (int o = 16; o; o >>= 1) {
        s1 += __shfl_xor_sync(0xffffffffu, s1, o);
        s2 += __shfl_xor_sync(0xffffffffu, s2, o);
    }
    if (lane == 0) { red[2][wrp] = s1; red[3][wrp] = s2; }
    __syncthreads();
    float z1 = 0.f, z2 = 0.f;
#pragma unroll
    for (int i = 0; i < 8; i++) { z1 += red[2][i]; z2 += red[3][i]; }

    as[tid] = (e1 / z1 + e2 / z2) * 0.5f / (float)S_LEN;
    __syncthreads();

    int d2 = blockIdx.x * 256 + tid;        // half2 index: 512 per b
    int s0 = blockIdx.z * S_PER_Z;
    const __half2* p = (const __half2*)g_Ah + (size_t)s0 * B_SZ * (D1 / 2) +
                       (size_t)b * (D1 / 2) + d2;
    float ax = 0.f, ay = 0.f;
#pragma unroll 16
    for (int s = 0; s < S_PER_Z; s++) {
        float2 v = __half22float2(p[(size_t)s * B_SZ * (D1 / 2)]);
        float w = as[s0 + s];
        ax += w * v.x; ay += w * v.y;
    }
    float* o = out + (size_t)b * D1 + d2 * 2;
    atomicAdd(o, ax);
    atomicAdd(o + 1, ay);
}

// ---------------- launch ----------------
extern "C" void kernel_launch(void* const* d_in, const int* in_sizes, int n_in,
                              void* d_out, int out_size) {
    const float* f1   = (const float*)d_in[0];
    const float* f2   = (const float*)d_in[1];
    const float* fseq = (const float*)d_in[2];
    const float* W11  = (const float*)d_in[3];
    const float* b11  = (const float*)d_in[4];
    const float* W12  = (const float*)d_in[5];
    const float* b12  = (const float*)d_in[6];
    const float* W21  = (const float*)d_in[7];
    const float* W22  = (const float*)d_in[9];
    float* out = (float*)d_out;

    cudaFuncSetAttribute(small_gemm_kernel, cudaFuncAttributeMaxDynamicSharedMemorySize, SMEM_BYTES_MAIN);
    cudaFuncSetAttribute(main_gemm_kernel,  cudaFuncAttributeMaxDynamicSharedMemorySize, SMEM_BYTES_MAIN);

    // prep (block-specialized: transpose + conversions + out zeroing), GEMMs, fused tail.
    prep_kernel<<<TRANS_BLOCKS + PREP_BLOCKS, 256>>>(fseq, f1, f2, b11, b12, W21, W22,
                                                     W11, W12, out);
    small_gemm_kernel<<<dim3(16, 1, 8), 256, SMEM_BYTES_MAIN>>>();
    main_gemm_kernel<<<dim3(16, 256), 256, SMEM_BYTES_MAIN>>>();
    softmax_wsum_kernel<<<dim3(2, 128, SPLIT_Z), 256>>>(out);
}